// round 14
// baseline (speedup 1.0000x reference)
#include <cuda_runtime.h>
#include <cuda_fp16.h>
#include <math.h>
#include <stdint.h>

// ---------------------------------------------------------------------------
// DifferentialAttention, folded algebra, fp16 hi/lo plane GEMMs.
// R14: pass-major MMA issue order (hh over all tiles, then hl, then lh) so
// same-accumulator MMAs are 8 independent MMAs apart -> RAW chain hidden.
//   qkv  = x @ Wqkv + bqkv          -> planes      [4096,1024]   (3-pass)
//   M    = Wv @ Wo                  -> fp32 (splitK=16) -> planes (3-pass)
//   V'   = x @ M                    -> single fp16 plane          (3-pass)
//   l1/l2 = Q@K^T * 0.125           -> fp32 (merged z=4)          (3-pass)
//   diff = softmax(l1)-lam*softmax(l2) -> single fp16 plane
//   out  = diff @ V' + cvec         -> fp32 (splitK=4)            (1-pass)
// ---------------------------------------------------------------------------

#define BM 128
#define BN 128
#define BKS 32              // K per stage (two 16-K sub-tiles)
#define NTH 512
#define NSTAGE 3
#define SUB_BYTES 16384
#define STAGE_BYTES 32768
#define DSMEM_BYTES (NSTAGE * STAGE_BYTES)   // 98304

typedef __half fp16;

// fp32 scratch
__device__ float g_M[512 * 512];
__device__ float g_l1[2 * 2048 * 2048];
__device__ float g_l2[2 * 2048 * 2048];
__device__ float g_lambda;
__device__ float g_cvec[512];
// fp16 hi/lo planes
__device__ fp16 g_xh[4096 * 512],  g_xl[4096 * 512];
__device__ fp16 g_wqh[512 * 1024], g_wql[512 * 1024];
__device__ fp16 g_wvh[512 * 8192], g_wvl[512 * 8192];
__device__ fp16 g_woh[8192 * 512], g_wol[8192 * 512];
__device__ fp16 g_qh[4096 * 1024], g_ql[4096 * 1024];
__device__ fp16 g_mh[512 * 512],   g_ml[512 * 512];
__device__ fp16 g_vph[4096 * 512];                 // single plane (feeds 1-pass final)
__device__ fp16 g_dh[2 * 2048 * 2048];             // single plane diff

// split two fp32 (x = even idx, y = odd idx) into packed fp16x2 hi and lo
__device__ __forceinline__ void split2(float x, float y, uint32_t& h, uint32_t& l) {
    __half2 H = __floats2half2_rn(x, y);
    float hx = __half2float(__low2half(H));
    float hy = __half2float(__high2half(H));
    __half2 L = __floats2half2_rn(x - hx, y - hy);
    h = *(uint32_t*)&H;
    l = *(uint32_t*)&L;
}
__device__ __forceinline__ uint32_t pack_h(float x, float y) {
    __half2 H = __floats2half2_rn(x, y);
    return *(uint32_t*)&H;
}

__device__ __forceinline__ void mma_fp16(float c[4],
                                         uint32_t a0, uint32_t a1, uint32_t a2, uint32_t a3,
                                         uint32_t b0, uint32_t b1) {
    asm volatile(
        "mma.sync.aligned.m16n8k16.row.col.f32.f16.f16.f32 "
        "{%0,%1,%2,%3}, {%4,%5,%6,%7}, {%8,%9}, {%0,%1,%2,%3};"
        : "+f"(c[0]), "+f"(c[1]), "+f"(c[2]), "+f"(c[3])
        : "r"(a0), "r"(a1), "r"(a2), "r"(a3), "r"(b0), "r"(b1));
}

__device__ __forceinline__ void ldsm_x4(uint32_t& r0, uint32_t& r1, uint32_t& r2, uint32_t& r3,
                                        uint32_t addr) {
    asm volatile("ldmatrix.sync.aligned.m8n8.x4.shared.b16 {%0,%1,%2,%3}, [%4];"
                 : "=r"(r0), "=r"(r1), "=r"(r2), "=r"(r3) : "r"(addr));
}
__device__ __forceinline__ void ldsm_x4t(uint32_t& r0, uint32_t& r1, uint32_t& r2, uint32_t& r3,
                                         uint32_t addr) {
    asm volatile("ldmatrix.sync.aligned.m8n8.x4.trans.shared.b16 {%0,%1,%2,%3}, [%4];"
                 : "=r"(r0), "=r"(r1), "=r"(r2), "=r"(r3) : "r"(addr));
}

__device__ __forceinline__ void cpa16(uint32_t smem, const void* gmem) {
    asm volatile("cp.async.ca.shared.global [%0], [%1], 16;" :: "r"(smem), "l"(gmem));
}
__device__ __forceinline__ void cpa_commit() { asm volatile("cp.async.commit_group;"); }
template <int N>
__device__ __forceinline__ void cpa_wait() { asm volatile("cp.async.wait_group %0;" :: "n"(N)); }

// ---------------------------------------------------------------------------
// fp16 plane GEMM. 512 threads, 16 warps (4x4 of 32x32 warp tiles).
// PASSES=3: A,B hi+lo planes, pass-major (hh all tiles, hl all, lh all).
// PASSES=1: hi planes only. Output: Ch -> fp16 plane (+Cl); splitk>1 ->
// fp32 atomicAdd; else fp32 store. Calt: merged logits (z>=2 -> +selOff).
// Sub-tile layout (16KB): A at +0 (plane*4096 + m*32 + swz16);
//                         B at +8192 (TB same; NN plane*4096 + k*256 + swz16).
// ---------------------------------------------------------------------------
template <bool TB, int PASSES>
__global__ __launch_bounds__(NTH, 1) void bf_gemm(
    const fp16* __restrict__ Ah, const fp16* __restrict__ Al,
    const fp16* __restrict__ Bh, const fp16* __restrict__ Bl,
    float* __restrict__ C, float* __restrict__ Calt,
    fp16* __restrict__ Ch, fp16* __restrict__ Cl,
    int K, int lda, int ldb, int ldc,
    long long sA, long long sB, long long sC,
    float alpha, const float* __restrict__ bias, int splitk, int selOff)
{
    int zb = blockIdx.z / splitk;
    const int kchunk = blockIdx.z % splitk;
    if (Calt) {
        int sel = zb >> 1;
        zb &= 1;
        if (sel) { Ah += selOff; Al += selOff; Bh += selOff; Bl += selOff; C = Calt; }
    }
    const int kc = K / splitk;
    const int kbeg = kchunk * kc;

    Ah += (long long)zb * sA; if (PASSES == 3) Al += (long long)zb * sA;
    Bh += (long long)zb * sB; if (PASSES == 3) Bl += (long long)zb * sB;
    if (C) C += (long long)zb * sC;
    if (Ch) { Ch += (long long)zb * sC; if (Cl) Cl += (long long)zb * sC; }

    const int brow = blockIdx.y * BM;
    const int bcol = blockIdx.x * BN;
    const int t = threadIdx.x;
    const int lane = t & 31;
    const int wid = t >> 5;
    const int wm = (wid >> 2) * 32;
    const int wn = (wid & 3) * 32;
    const int q = lane & 3;
    const int r = lane >> 2;
    const int lg = lane >> 3;
    const int lr = lane & 7;

    extern __shared__ __align__(128) char sm[];
    const uint32_t sm0 = (uint32_t)__cvta_generic_to_shared(sm);

    float acc[2][4][4];
#pragma unroll
    for (int i = 0; i < 2; i++)
#pragma unroll
        for (int j = 0; j < 4; j++)
#pragma unroll
            for (int c = 0; c < 4; c++) acc[i][j][c] = 0.f;

    // cp.async: per sub-tile, 512 16B-chunks per operand (hi+lo) or 256 (hi).
    const int pl_  = t >> 8;
    const int rem_ = t & 255;
    auto load_stage = [&](int st, int k0) {
        uint32_t sbase = sm0 + (uint32_t)(st * STAGE_BYTES);
#pragma unroll
        for (int sub = 0; sub < 2; sub++) {
            uint32_t base = sbase + (uint32_t)(sub * SUB_BYTES);
            int ks = k0 + sub * 16;
            if (PASSES == 3 || pl_ == 0) {
                {
                    int m = rem_ >> 1, half = rem_ & 1;
                    const fp16* src = (pl_ ? Al : Ah) + (long long)(brow + m) * lda + ks + half * 8;
                    cpa16(base + (uint32_t)(pl_ * 4096 + m * 32 + ((half ^ ((m >> 2) & 1)) * 16)), src);
                }
                if (TB) {
                    int n = rem_ >> 1, half = rem_ & 1;
                    const fp16* src = (pl_ ? Bl : Bh) + (long long)(bcol + n) * ldb + ks + half * 8;
                    cpa16(base + (uint32_t)(8192 + pl_ * 4096 + n * 32 + ((half ^ ((n >> 2) & 1)) * 16)), src);
                } else {
                    int kk = rem_ >> 4, j = rem_ & 15;
                    const fp16* src = (pl_ ? Bl : Bh) + (long long)(ks + kk) * ldb + bcol + j * 8;
                    cpa16(base + (uint32_t)(8192 + pl_ * 4096 + kk * 256 + ((j ^ (kk & 7)) * 16)), src);
                }
            }
        }
        cpa_commit();
    };

    // compute one 16-K sub-tile at smem offset `base`, pass-major MMA order
    auto compute_sub = [&](uint32_t base) {
        const int NPL = (PASSES == 3) ? 2 : 1;
        uint32_t Bf[2][4][2];
#pragma unroll
        for (int pl = 0; pl < NPL; pl++) {
#pragma unroll
            for (int pair = 0; pair < 2; pair++) {
                int nl = pair * 2, nh = pair * 2 + 1;
                if (TB) {
                    int row = wn + pair * 16 + lr + (lg & 1) * 8;
                    int half = lg >> 1;
                    uint32_t a = base + (uint32_t)(8192 + pl * 4096 + row * 32 +
                                                   ((half ^ ((row >> 2) & 1)) * 16));
                    ldsm_x4(Bf[pl][nl][0], Bf[pl][nh][0], Bf[pl][nl][1], Bf[pl][nh][1], a);
                } else {
                    int krow = lr + (lg & 1) * 8;
                    int j = (wn >> 3) + pair * 2 + (lg >> 1);
                    uint32_t a = base + (uint32_t)(8192 + pl * 4096 + krow * 256 +
                                                   ((j ^ (krow & 7)) * 16));
                    ldsm_x4t(Bf[pl][nl][0], Bf[pl][nl][1], Bf[pl][nh][0], Bf[pl][nh][1], a);
                }
            }
        }
        // A fragments for both mt, both planes, held across passes
        uint32_t Af[2][2][4];   // [plane][mt][reg]
#pragma unroll
        for (int mt = 0; mt < 2; mt++) {
            int row = wm + mt * 16 + lr + (lg & 1) * 8;
            int half = lg >> 1;
            uint32_t swz = (uint32_t)((half ^ ((row >> 2) & 1)) * 16);
            ldsm_x4(Af[0][mt][0], Af[0][mt][1], Af[0][mt][2], Af[0][mt][3],
                    base + (uint32_t)(row * 32) + swz);
            if (PASSES == 3)
                ldsm_x4(Af[1][mt][0], Af[1][mt][1], Af[1][mt][2], Af[1][mt][3],
                        base + (uint32_t)(4096 + row * 32) + swz);
        }
        // pass hh: 8 independent MMAs
#pragma unroll
        for (int mt = 0; mt < 2; mt++)
#pragma unroll
            for (int nt = 0; nt < 4; nt++)
                mma_fp16(acc[mt][nt], Af[0][mt][0], Af[0][mt][1], Af[0][mt][2], Af[0][mt][3],
                         Bf[0][nt][0], Bf[0][nt][1]);
        if (PASSES == 3) {
            // pass hl
#pragma unroll
            for (int mt = 0; mt < 2; mt++)
#pragma unroll
                for (int nt = 0; nt < 4; nt++)
                    mma_fp16(acc[mt][nt], Af[0][mt][0], Af[0][mt][1], Af[0][mt][2], Af[0][mt][3],
                             Bf[1][nt][0], Bf[1][nt][1]);
            // pass lh
#pragma unroll
            for (int mt = 0; mt < 2; mt++)
#pragma unroll
                for (int nt = 0; nt < 4; nt++)
                    mma_fp16(acc[mt][nt], Af[1][mt][0], Af[1][mt][1], Af[1][mt][2], Af[1][mt][3],
                             Bf[0][nt][0], Bf[0][nt][1]);
        }
    };

    const int nIter = kc / BKS;
    load_stage(0, kbeg);
    if (nIter > 1) load_stage(1, kbeg + BKS);

    for (int it = 0; it < nIter; it++) {
        if (it + 1 < nIter) cpa_wait<1>(); else cpa_wait<0>();
        __syncthreads();
        if (it + 2 < nIter) load_stage((it + 2) % NSTAGE, kbeg + (it + 2) * BKS);

        uint32_t sbase = sm0 + (uint32_t)((it % NSTAGE) * STAGE_BYTES);
        compute_sub(sbase);
        compute_sub(sbase + SUB_BYTES);
        __syncthreads();
    }

    // ---- epilogue ----
#pragma unroll
    for (int mt = 0; mt < 2; mt++) {
#pragma unroll
        for (int nt = 0; nt < 4; nt++) {
            int row = brow + wm + mt * 16 + r;
            int col = bcol + wn + nt * 8 + 2 * q;
            float b0 = 0.f, b1 = 0.f;
            if (bias && kchunk == 0) { b0 = bias[col]; b1 = bias[col + 1]; }
            float v0 = alpha * acc[mt][nt][0] + b0;
            float v1 = alpha * acc[mt][nt][1] + b1;
            float v2 = alpha * acc[mt][nt][2] + b0;
            float v3 = alpha * acc[mt][nt][3] + b1;
            if (Ch) {
                if (Cl) {
                    uint32_t h, l;
                    split2(v0, v1, h, l);
                    *(uint32_t*)&Ch[(long long)row * ldc + col] = h;
                    *(uint32_t*)&Cl[(long long)row * ldc + col] = l;
                    split2(v2, v3, h, l);
                    *(uint32_t*)&Ch[(long long)(row + 8) * ldc + col] = h;
                    *(uint32_t*)&Cl[(long long)(row + 8) * ldc + col] = l;
                } else {
                    *(uint32_t*)&Ch[(long long)row * ldc + col] = pack_h(v0, v1);
                    *(uint32_t*)&Ch[(long long)(row + 8) * ldc + col] = pack_h(v2, v3);
                }
            } else if (splitk > 1) {
                atomicAdd(&C[(long long)row * ldc + col], v0);
                atomicAdd(&C[(long long)row * ldc + col + 1], v1);
                atomicAdd(&C[(long long)(row + 8) * ldc + col], v2);
                atomicAdd(&C[(long long)(row + 8) * ldc + col + 1], v3);
            } else {
                *(float2*)&C[(long long)row * ldc + col] = make_float2(v0, v1);
                *(float2*)&C[(long long)(row + 8) * ldc + col] = make_float2(v2, v3);
            }
        }
    }
}

// ---------------------------------------------------------------------------
__global__ void split_kernel(const float4* __restrict__ src,
                             uint2* __restrict__ h, uint2* __restrict__ l, int n4)
{
    int i = blockIdx.x * blockDim.x + threadIdx.x;
    if (i < n4) {
        float4 v = src[i];
        uint32_t h0, l0, h1, l1;
        split2(v.x, v.y, h0, l0);
        split2(v.z, v.w, h1, l1);
        h[i] = make_uint2(h0, h1);
        l[i] = make_uint2(l0, l1);
    }
}

__global__ void lambda_kernel(const float* __restrict__ lq1, const float* __restrict__ lk1,
                              const float* __restrict__ lq2, const float* __restrict__ lk2)
{
    if (threadIdx.x == 0) {
        float d1 = 0.f, d2 = 0.f;
        for (int i = 0; i < 64; i++) {
            d1 += lq1[i] * lk1[i];
            d2 += lq2[i] * lk2[i];
        }
        g_lambda = expf(d1) - expf(d2) + (0.8f - 0.6f * expf(-0.3f * 0.0f));
    }
}

// cvec[n] = bo[n] + (1-lam) * sum_k bv[k]*Wo[k,n]; one block per n.
__global__ __launch_bounds__(256) void cvec_kernel(
    const float* __restrict__ bv, const float* __restrict__ Wo,
    const float* __restrict__ bo)
{
    const int n = blockIdx.x;
    const int t = threadIdx.x;
    float s = 0.f;
    for (int k = t; k < 8192; k += 256)
        s += bv[k] * Wo[(long long)k * 512 + n];
    __shared__ float red[256];
    red[t] = s;
    __syncthreads();
    for (int o = 128; o; o >>= 1) {
        if (t < o) red[t] += red[t + o];
        __syncthreads();
    }
    if (t == 0) g_cvec[n] = bo[n] + (1.f - g_lambda) * red[0];
}

// ---------------------------------------------------------------------------
// Fused dual softmax + differential combine; writes single fp16 plane.
// ---------------------------------------------------------------------------
__global__ __launch_bounds__(256) void softmax_diff_kernel(
    const float* __restrict__ l1, const float* __restrict__ l2,
    fp16* __restrict__ dh)
{
    long long row = blockIdx.x;
    const float* r1 = l1 + row * 2048;
    const float* r2 = l2 + row * 2048;
    const int t = threadIdx.x;
    const int lane = t & 31, warp = t >> 5;

    float v1[8], v2[8];
    *(float4*)&v1[0] = *(const float4*)&r1[t * 8];
    *(float4*)&v1[4] = *(const float4*)&r1[t * 8 + 4];
    *(float4*)&v2[0] = *(const float4*)&r2[t * 8];
    *(float4*)&v2[4] = *(const float4*)&r2[t * 8 + 4];

    float m1 = -1e30f, m2 = -1e30f;
#pragma unroll
    for (int i = 0; i < 8; i++) {
        m1 = fmaxf(m1, v1[i]);
        m2 = fmaxf(m2, v2[i]);
    }
#pragma unroll
    for (int o = 16; o; o >>= 1) {
        m1 = fmaxf(m1, __shfl_xor_sync(0xffffffffu, m1, o));
        m2 = fmaxf(m2, __shfl_xor_sync(0xffffffffu, m2, o));
    }
    __shared__ float s1[8], s2[8];
    if (lane == 0) { s1[warp] = m1; s2[warp] = m2; }
    __syncthreads();
    m1 = s1[0]; m2 = s2[0];
#pragma unroll
    for (int w = 1; w < 8; w++) {
        m1 = fmaxf(m1, s1[w]);
        m2 = fmaxf(m2, s2[w]);
    }

    float e1[8], e2[8];
    float sum1 = 0.f, sum2 = 0.f;
#pragma unroll
    for (int i = 0; i < 8; i++) {
        e1[i] = __expf(v1[i] - m1);
        e2[i] = __expf(v2[i] - m2);
        sum1 += e1[i];
        sum2 += e2[i];
    }
#pragma unroll
    for (int o = 16; o; o >>= 1) {
        sum1 += __shfl_xor_sync(0xffffffffu, sum1, o);
        sum2 += __shfl_xor_sync(0xffffffffu, sum2, o);
    }
    __syncthreads();
    if (lane == 0) { s1[warp] = sum1; s2[warp] = sum2; }
    __syncthreads();
    sum1 = 0.f; sum2 = 0.f;
#pragma unroll
    for (int w = 0; w < 8; w++) { sum1 += s1[w]; sum2 += s2[w]; }

    const float inv1 = 1.f / sum1;
    const float inv2 = g_lambda / sum2;
    uint4 hv;
    hv.x = pack_h(e1[0] * inv1 - e2[0] * inv2, e1[1] * inv1 - e2[1] * inv2);
    hv.y = pack_h(e1[2] * inv1 - e2[2] * inv2, e1[3] * inv1 - e2[3] * inv2);
    hv.z = pack_h(e1[4] * inv1 - e2[4] * inv2, e1[5] * inv1 - e2[5] * inv2);
    hv.w = pack_h(e1[6] * inv1 - e2[6] * inv2, e1[7] * inv1 - e2[7] * inv2);
    *(uint4*)&dh[row * 2048 + t * 8] = hv;
}

// ---------------------------------------------------------------------------
extern "C" void kernel_launch(void* const* d_in, const int* in_sizes, int n_in,
                              void* d_out, int out_size)
{
    const float* x    = (const float*)d_in[0];
    const float* Wqkv = (const float*)d_in[1];
    const float* bqkv = (const float*)d_in[2];
    const float* Wv   = (const float*)d_in[3];
    const float* bv   = (const float*)d_in[4];
    const float* Wo   = (const float*)d_in[5];
    const float* bo   = (const float*)d_in[6];
    const float* lq1  = (const float*)d_in[7];
    const float* lk1  = (const float*)d_in[8];
    const float* lq2  = (const float*)d_in[9];
    const float* lk2  = (const float*)d_in[10];
    float* out = (float*)d_out;

    cudaFuncSetAttribute(bf_gemm<false, 3>, cudaFuncAttributeMaxDynamicSharedMemorySize, DSMEM_BYTES);
    cudaFuncSetAttribute(bf_gemm<true, 3>,  cudaFuncAttributeMaxDynamicSharedMemorySize, DSMEM_BYTES);
    cudaFuncSetAttribute(bf_gemm<false, 1>, cudaFuncAttributeMaxDynamicSharedMemorySize, DSMEM_BYTES);

    float *Mm, *l1, *l2, *cvec;
    fp16 *xh, *xl, *wqh, *wql, *wvh, *wvl, *woh, *wol;
    fp16 *qh, *ql, *mh, *ml, *vph, *dh;
    cudaGetSymbolAddress((void**)&Mm,  g_M);
    cudaGetSymbolAddress((void**)&l1,  g_l1);
    cudaGetSymbolAddress((void**)&l2,  g_l2);
    cudaGetSymbolAddress((void**)&cvec, g_cvec);
    cudaGetSymbolAddress((void**)&xh,  g_xh);   cudaGetSymbolAddress((void**)&xl,  g_xl);
    cudaGetSymbolAddress((void**)&wqh, g_wqh);  cudaGetSymbolAddress((void**)&wql, g_wql);
    cudaGetSymbolAddress((void**)&wvh, g_wvh);  cudaGetSymbolAddress((void**)&wvl, g_wvl);
    cudaGetSymbolAddress((void**)&woh, g_woh);  cudaGetSymbolAddress((void**)&wol, g_wol);
    cudaGetSymbolAddress((void**)&qh,  g_qh);   cudaGetSymbolAddress((void**)&ql,  g_ql);
    cudaGetSymbolAddress((void**)&mh,  g_mh);   cudaGetSymbolAddress((void**)&ml,  g_ml);
    cudaGetSymbolAddress((void**)&vph, g_vph);
    cudaGetSymbolAddress((void**)&dh,  g_dh);

    const long long SQ  = 2048LL * 1024;
    const long long SL  = 2048LL * 2048;
    const long long SV  = 2048LL * 512;

    lambda_kernel<<<1, 32>>>(lq1, lk1, lq2, lk2);
    split_kernel<<<2048, 256>>>((const float4*)x,    (uint2*)xh,  (uint2*)xl,  4096 * 512 / 4);
    split_kernel<<<512,  256>>>((const float4*)Wqkv, (uint2*)wqh, (uint2*)wql, 512 * 1024 / 4);
    split_kernel<<<4096, 256>>>((const float4*)Wv,   (uint2*)wvh, (uint2*)wvl, 512 * 8192 / 4);
    split_kernel<<<4096, 256>>>((const float4*)Wo,   (uint2*)woh, (uint2*)wol, 8192 * 512 / 4);

    // qkv = x @ Wqkv + bqkv -> planes  [4096,1024]   (3-pass)
    bf_gemm<false, 3><<<dim3(8, 32, 1), NTH, DSMEM_BYTES>>>(
        xh, xl, wqh, wql, nullptr, nullptr, qh, ql,
        512, 512, 1024, 1024, 0, 0, 0, 1.f, bqkv, 1, 0);

    // M = Wv @ Wo  (fp32, splitK=16), then split to planes
    cudaMemsetAsync(Mm, 0, 512 * 512 * sizeof(float));
    bf_gemm<false, 3><<<dim3(4, 4, 16), NTH, DSMEM_BYTES>>>(
        wvh, wvl, woh, wol, Mm, nullptr, nullptr, nullptr,
        8192, 8192, 512, 512, 0, 0, 0, 1.f, nullptr, 16, 0);
    split_kernel<<<256, 256>>>((const float4*)Mm, (uint2*)mh, (uint2*)ml, 512 * 512 / 4);

    // V' = x @ M -> single fp16 plane  [4096,512]   (3-pass compute)
    bf_gemm<false, 3><<<dim3(4, 32, 1), NTH, DSMEM_BYTES>>>(
        xh, xl, mh, ml, nullptr, nullptr, vph, nullptr,
        512, 512, 512, 512, 0, 0, 0, 1.f, nullptr, 1, 0);

    // logits merged (z=0,1 -> l1 via Q1/K1; z=2,3 -> l2 via +256 offset)
    bf_gemm<true, 3><<<dim3(16, 16, 4), NTH, DSMEM_BYTES>>>(
        qh + 0, ql + 0, qh + 512, ql + 512, l1, l2, nullptr, nullptr,
        256, 1024, 1024, 2048, SQ, SQ, SL, 0.125f, nullptr, 1, 256);

    // cvec (needed only before final)
    cvec_kernel<<<512, 256>>>(bv, Wo, bo);

    // diff = softmax(l1) - lam*softmax(l2) -> single fp16 plane
    softmax_diff_kernel<<<4096, 256>>>(l1, l2, dh);

    // out = diff @ V' + cvec  (fp32, 1-pass fp16, splitK=4)
    cudaMemsetAsync(out, 0, 2 * 2048 * 512 * sizeof(float));
    bf_gemm<false, 1><<<dim3(4, 16, 8), NTH, DSMEM_BYTES>>>(
        dh, nullptr, vph, nullptr, out, nullptr, nullptr, nullptr,
        2048, 2048, 512, 512, SL, SV, SV, 1.f, cvec, 4, 0);
}

// round 15
// speedup vs baseline: 1.0158x; 1.0158x over previous
#include <cuda_runtime.h>
#include <cuda_fp16.h>
#include <math.h>
#include <stdint.h>

// ---------------------------------------------------------------------------
// DifferentialAttention, folded algebra, fp16 hi/lo plane GEMMs.
// R15: launch order tuned so ncu (empirically 4th launch) profiles the logits
// GEMM; split kernels widened to 8 floats/thread; final GEMM splitK=2.
//   qkv  = x @ Wqkv + bqkv          -> planes      [4096,1024]   (3-pass)
//   M    = Wv @ Wo                  -> fp32 (splitK=16) -> planes (3-pass)
//   V'   = x @ M                    -> single fp16 plane          (3-pass)
//   l1/l2 = Q@K^T * 0.125           -> fp32 (merged z=4)          (3-pass)
//   diff = softmax(l1)-lam*softmax(l2) -> single fp16 plane
//   out  = diff @ V' + cvec         -> fp32 (splitK=2)            (1-pass)
// ---------------------------------------------------------------------------

#define BM 128
#define BN 128
#define BKS 32
#define NTH 512
#define NSTAGE 3
#define SUB_BYTES 16384
#define STAGE_BYTES 32768
#define DSMEM_BYTES (NSTAGE * STAGE_BYTES)   // 98304

typedef __half fp16;

// fp32 scratch
__device__ float g_M[512 * 512];
__device__ float g_l1[2 * 2048 * 2048];
__device__ float g_l2[2 * 2048 * 2048];
__device__ float g_lambda;
__device__ float g_cvec[512];
// fp16 hi/lo planes
__device__ fp16 g_xh[4096 * 512],  g_xl[4096 * 512];
__device__ fp16 g_wqh[512 * 1024], g_wql[512 * 1024];
__device__ fp16 g_wvh[512 * 8192], g_wvl[512 * 8192];
__device__ fp16 g_woh[8192 * 512], g_wol[8192 * 512];
__device__ fp16 g_qh[4096 * 1024], g_ql[4096 * 1024];
__device__ fp16 g_mh[512 * 512],   g_ml[512 * 512];
__device__ fp16 g_vph[4096 * 512];
__device__ fp16 g_dh[2 * 2048 * 2048];

__device__ __forceinline__ void split2(float x, float y, uint32_t& h, uint32_t& l) {
    __half2 H = __floats2half2_rn(x, y);
    float hx = __half2float(__low2half(H));
    float hy = __half2float(__high2half(H));
    __half2 L = __floats2half2_rn(x - hx, y - hy);
    h = *(uint32_t*)&H;
    l = *(uint32_t*)&L;
}
__device__ __forceinline__ uint32_t pack_h(float x, float y) {
    __half2 H = __floats2half2_rn(x, y);
    return *(uint32_t*)&H;
}

__device__ __forceinline__ void mma_fp16(float c[4],
                                         uint32_t a0, uint32_t a1, uint32_t a2, uint32_t a3,
                                         uint32_t b0, uint32_t b1) {
    asm volatile(
        "mma.sync.aligned.m16n8k16.row.col.f32.f16.f16.f32 "
        "{%0,%1,%2,%3}, {%4,%5,%6,%7}, {%8,%9}, {%0,%1,%2,%3};"
        : "+f"(c[0]), "+f"(c[1]), "+f"(c[2]), "+f"(c[3])
        : "r"(a0), "r"(a1), "r"(a2), "r"(a3), "r"(b0), "r"(b1));
}

__device__ __forceinline__ void ldsm_x4(uint32_t& r0, uint32_t& r1, uint32_t& r2, uint32_t& r3,
                                        uint32_t addr) {
    asm volatile("ldmatrix.sync.aligned.m8n8.x4.shared.b16 {%0,%1,%2,%3}, [%4];"
                 : "=r"(r0), "=r"(r1), "=r"(r2), "=r"(r3) : "r"(addr));
}
__device__ __forceinline__ void ldsm_x4t(uint32_t& r0, uint32_t& r1, uint32_t& r2, uint32_t& r3,
                                         uint32_t addr) {
    asm volatile("ldmatrix.sync.aligned.m8n8.x4.trans.shared.b16 {%0,%1,%2,%3}, [%4];"
                 : "=r"(r0), "=r"(r1), "=r"(r2), "=r"(r3) : "r"(addr));
}

__device__ __forceinline__ void cpa16(uint32_t smem, const void* gmem) {
    asm volatile("cp.async.ca.shared.global [%0], [%1], 16;" :: "r"(smem), "l"(gmem));
}
__device__ __forceinline__ void cpa_commit() { asm volatile("cp.async.commit_group;"); }
template <int N>
__device__ __forceinline__ void cpa_wait() { asm volatile("cp.async.wait_group %0;" :: "n"(N)); }

// ---------------------------------------------------------------------------
// fp16 plane GEMM. 512 threads, 16 warps (4x4 of 32x32 warp tiles).
// PASSES=3: hi+lo planes, pass-major. PASSES=1: hi planes only.
// ---------------------------------------------------------------------------
template <bool TB, int PASSES>
__global__ __launch_bounds__(NTH, 1) void bf_gemm(
    const fp16* __restrict__ Ah, const fp16* __restrict__ Al,
    const fp16* __restrict__ Bh, const fp16* __restrict__ Bl,
    float* __restrict__ C, float* __restrict__ Calt,
    fp16* __restrict__ Ch, fp16* __restrict__ Cl,
    int K, int lda, int ldb, int ldc,
    long long sA, long long sB, long long sC,
    float alpha, const float* __restrict__ bias, int splitk, int selOff)
{
    int zb = blockIdx.z / splitk;
    const int kchunk = blockIdx.z % splitk;
    if (Calt) {
        int sel = zb >> 1;
        zb &= 1;
        if (sel) { Ah += selOff; Al += selOff; Bh += selOff; Bl += selOff; C = Calt; }
    }
    const int kc = K / splitk;
    const int kbeg = kchunk * kc;

    Ah += (long long)zb * sA; if (PASSES == 3) Al += (long long)zb * sA;
    Bh += (long long)zb * sB; if (PASSES == 3) Bl += (long long)zb * sB;
    if (C) C += (long long)zb * sC;
    if (Ch) { Ch += (long long)zb * sC; if (Cl) Cl += (long long)zb * sC; }

    const int brow = blockIdx.y * BM;
    const int bcol = blockIdx.x * BN;
    const int t = threadIdx.x;
    const int lane = t & 31;
    const int wid = t >> 5;
    const int wm = (wid >> 2) * 32;
    const int wn = (wid & 3) * 32;
    const int q = lane & 3;
    const int r = lane >> 2;
    const int lg = lane >> 3;
    const int lr = lane & 7;

    extern __shared__ __align__(128) char sm[];
    const uint32_t sm0 = (uint32_t)__cvta_generic_to_shared(sm);

    float acc[2][4][4];
#pragma unroll
    for (int i = 0; i < 2; i++)
#pragma unroll
        for (int j = 0; j < 4; j++)
#pragma unroll
            for (int c = 0; c < 4; c++) acc[i][j][c] = 0.f;

    const int pl_  = t >> 8;
    const int rem_ = t & 255;
    auto load_stage = [&](int st, int k0) {
        uint32_t sbase = sm0 + (uint32_t)(st * STAGE_BYTES);
#pragma unroll
        for (int sub = 0; sub < 2; sub++) {
            uint32_t base = sbase + (uint32_t)(sub * SUB_BYTES);
            int ks = k0 + sub * 16;
            if (PASSES == 3 || pl_ == 0) {
                {
                    int m = rem_ >> 1, half = rem_ & 1;
                    const fp16* src = (pl_ ? Al : Ah) + (long long)(brow + m) * lda + ks + half * 8;
                    cpa16(base + (uint32_t)(pl_ * 4096 + m * 32 + ((half ^ ((m >> 2) & 1)) * 16)), src);
                }
                if (TB) {
                    int n = rem_ >> 1, half = rem_ & 1;
                    const fp16* src = (pl_ ? Bl : Bh) + (long long)(bcol + n) * ldb + ks + half * 8;
                    cpa16(base + (uint32_t)(8192 + pl_ * 4096 + n * 32 + ((half ^ ((n >> 2) & 1)) * 16)), src);
                } else {
                    int kk = rem_ >> 4, j = rem_ & 15;
                    const fp16* src = (pl_ ? Bl : Bh) + (long long)(ks + kk) * ldb + bcol + j * 8;
                    cpa16(base + (uint32_t)(8192 + pl_ * 4096 + kk * 256 + ((j ^ (kk & 7)) * 16)), src);
                }
            }
        }
        cpa_commit();
    };

    auto compute_sub = [&](uint32_t base) {
        const int NPL = (PASSES == 3) ? 2 : 1;
        uint32_t Bf[2][4][2];
#pragma unroll
        for (int pl = 0; pl < NPL; pl++) {
#pragma unroll
            for (int pair = 0; pair < 2; pair++) {
                int nl = pair * 2, nh = pair * 2 + 1;
                if (TB) {
                    int row = wn + pair * 16 + lr + (lg & 1) * 8;
                    int half = lg >> 1;
                    uint32_t a = base + (uint32_t)(8192 + pl * 4096 + row * 32 +
                                                   ((half ^ ((row >> 2) & 1)) * 16));
                    ldsm_x4(Bf[pl][nl][0], Bf[pl][nh][0], Bf[pl][nl][1], Bf[pl][nh][1], a);
                } else {
                    int krow = lr + (lg & 1) * 8;
                    int j = (wn >> 3) + pair * 2 + (lg >> 1);
                    uint32_t a = base + (uint32_t)(8192 + pl * 4096 + krow * 256 +
                                                   ((j ^ (krow & 7)) * 16));
                    ldsm_x4t(Bf[pl][nl][0], Bf[pl][nl][1], Bf[pl][nh][0], Bf[pl][nh][1], a);
                }
            }
        }
        uint32_t Af[2][2][4];
#pragma unroll
        for (int mt = 0; mt < 2; mt++) {
            int row = wm + mt * 16 + lr + (lg & 1) * 8;
            int half = lg >> 1;
            uint32_t swz = (uint32_t)((half ^ ((row >> 2) & 1)) * 16);
            ldsm_x4(Af[0][mt][0], Af[0][mt][1], Af[0][mt][2], Af[0][mt][3],
                    base + (uint32_t)(row * 32) + swz);
            if (PASSES == 3)
                ldsm_x4(Af[1][mt][0], Af[1][mt][1], Af[1][mt][2], Af[1][mt][3],
                        base + (uint32_t)(4096 + row * 32) + swz);
        }
#pragma unroll
        for (int mt = 0; mt < 2; mt++)
#pragma unroll
            for (int nt = 0; nt < 4; nt++)
                mma_fp16(acc[mt][nt], Af[0][mt][0], Af[0][mt][1], Af[0][mt][2], Af[0][mt][3],
                         Bf[0][nt][0], Bf[0][nt][1]);
        if (PASSES == 3) {
#pragma unroll
            for (int mt = 0; mt < 2; mt++)
#pragma unroll
                for (int nt = 0; nt < 4; nt++)
                    mma_fp16(acc[mt][nt], Af[0][mt][0], Af[0][mt][1], Af[0][mt][2], Af[0][mt][3],
                             Bf[1][nt][0], Bf[1][nt][1]);
#pragma unroll
            for (int mt = 0; mt < 2; mt++)
#pragma unroll
                for (int nt = 0; nt < 4; nt++)
                    mma_fp16(acc[mt][nt], Af[1][mt][0], Af[1][mt][1], Af[1][mt][2], Af[1][mt][3],
                             Bf[0][nt][0], Bf[0][nt][1]);
        }
    };

    const int nIter = kc / BKS;
    load_stage(0, kbeg);
    if (nIter > 1) load_stage(1, kbeg + BKS);

    for (int it = 0; it < nIter; it++) {
        if (it + 1 < nIter) cpa_wait<1>(); else cpa_wait<0>();
        __syncthreads();
        if (it + 2 < nIter) load_stage((it + 2) % NSTAGE, kbeg + (it + 2) * BKS);

        uint32_t sbase = sm0 + (uint32_t)((it % NSTAGE) * STAGE_BYTES);
        compute_sub(sbase);
        compute_sub(sbase + SUB_BYTES);
        __syncthreads();
    }

#pragma unroll
    for (int mt = 0; mt < 2; mt++) {
#pragma unroll
        for (int nt = 0; nt < 4; nt++) {
            int row = brow + wm + mt * 16 + r;
            int col = bcol + wn + nt * 8 + 2 * q;
            float b0 = 0.f, b1 = 0.f;
            if (bias && kchunk == 0) { b0 = bias[col]; b1 = bias[col + 1]; }
            float v0 = alpha * acc[mt][nt][0] + b0;
            float v1 = alpha * acc[mt][nt][1] + b1;
            float v2 = alpha * acc[mt][nt][2] + b0;
            float v3 = alpha * acc[mt][nt][3] + b1;
            if (Ch) {
                if (Cl) {
                    uint32_t h, l;
                    split2(v0, v1, h, l);
                    *(uint32_t*)&Ch[(long long)row * ldc + col] = h;
                    *(uint32_t*)&Cl[(long long)row * ldc + col] = l;
                    split2(v2, v3, h, l);
                    *(uint32_t*)&Ch[(long long)(row + 8) * ldc + col] = h;
                    *(uint32_t*)&Cl[(long long)(row + 8) * ldc + col] = l;
                } else {
                    *(uint32_t*)&Ch[(long long)row * ldc + col] = pack_h(v0, v1);
                    *(uint32_t*)&Ch[(long long)(row + 8) * ldc + col] = pack_h(v2, v3);
                }
            } else if (splitk > 1) {
                atomicAdd(&C[(long long)row * ldc + col], v0);
                atomicAdd(&C[(long long)row * ldc + col + 1], v1);
                atomicAdd(&C[(long long)(row + 8) * ldc + col], v2);
                atomicAdd(&C[(long long)(row + 8) * ldc + col + 1], v3);
            } else {
                *(float2*)&C[(long long)row * ldc + col] = make_float2(v0, v1);
                *(float2*)&C[(long long)(row + 8) * ldc + col] = make_float2(v2, v3);
            }
        }
    }
}

// ---------------------------------------------------------------------------
// Elementwise fp32 -> fp16 hi/lo plane split, 8 floats/thread (n8 = n/8).
// ---------------------------------------------------------------------------
__global__ void split_kernel(const float4* __restrict__ src,
                             uint4* __restrict__ h, uint4* __restrict__ l, int n8)
{
    int i = blockIdx.x * blockDim.x + threadIdx.x;
    if (i < n8) {
        float4 v0 = src[2 * i];
        float4 v1 = src[2 * i + 1];
        uint4 hv, lv;
        split2(v0.x, v0.y, hv.x, lv.x);
        split2(v0.z, v0.w, hv.y, lv.y);
        split2(v1.x, v1.y, hv.z, lv.z);
        split2(v1.z, v1.w, hv.w, lv.w);
        h[i] = hv;
        l[i] = lv;
    }
}

__global__ void lambda_kernel(const float* __restrict__ lq1, const float* __restrict__ lk1,
                              const float* __restrict__ lq2, const float* __restrict__ lk2)
{
    if (threadIdx.x == 0) {
        float d1 = 0.f, d2 = 0.f;
        for (int i = 0; i < 64; i++) {
            d1 += lq1[i] * lk1[i];
            d2 += lq2[i] * lk2[i];
        }
        g_lambda = expf(d1) - expf(d2) + (0.8f - 0.6f * expf(-0.3f * 0.0f));
    }
}

// cvec[n] = bo[n] + (1-lam) * sum_k bv[k]*Wo[k,n]; one block per n.
__global__ __launch_bounds__(256) void cvec_kernel(
    const float* __restrict__ bv, const float* __restrict__ Wo,
    const float* __restrict__ bo)
{
    const int n = blockIdx.x;
    const int t = threadIdx.x;
    float s = 0.f;
    for (int k = t; k < 8192; k += 256)
        s += bv[k] * Wo[(long long)k * 512 + n];
    __shared__ float red[256];
    red[t] = s;
    __syncthreads();
    for (int o = 128; o; o >>= 1) {
        if (t < o) red[t] += red[t + o];
        __syncthreads();
    }
    if (t == 0) g_cvec[n] = bo[n] + (1.f - g_lambda) * red[0];
}

// ---------------------------------------------------------------------------
__global__ __launch_bounds__(256) void softmax_diff_kernel(
    const float* __restrict__ l1, const float* __restrict__ l2,
    fp16* __restrict__ dh)
{
    long long row = blockIdx.x;
    const float* r1 = l1 + row * 2048;
    const float* r2 = l2 + row * 2048;
    const int t = threadIdx.x;
    const int lane = t & 31, warp = t >> 5;

    float v1[8], v2[8];
    *(float4*)&v1[0] = *(const float4*)&r1[t * 8];
    *(float4*)&v1[4] = *(const float4*)&r1[t * 8 + 4];
    *(float4*)&v2[0] = *(const float4*)&r2[t * 8];
    *(float4*)&v2[4] = *(const float4*)&r2[t * 8 + 4];

    float m1 = -1e30f, m2 = -1e30f;
#pragma unroll
    for (int i = 0; i < 8; i++) {
        m1 = fmaxf(m1, v1[i]);
        m2 = fmaxf(m2, v2[i]);
    }
#pragma unroll
    for (int o = 16; o; o >>= 1) {
        m1 = fmaxf(m1, __shfl_xor_sync(0xffffffffu, m1, o));
        m2 = fmaxf(m2, __shfl_xor_sync(0xffffffffu, m2, o));
    }
    __shared__ float s1[8], s2[8];
    if (lane == 0) { s1[warp] = m1; s2[warp] = m2; }
    __syncthreads();
    m1 = s1[0]; m2 = s2[0];
#pragma unroll
    for (int w = 1; w < 8; w++) {
        m1 = fmaxf(m1, s1[w]);
        m2 = fmaxf(m2, s2[w]);
    }

    float e1[8], e2[8];
    float sum1 = 0.f, sum2 = 0.f;
#pragma unroll
    for (int i = 0; i < 8; i++) {
        e1[i] = __expf(v1[i] - m1);
        e2[i] = __expf(v2[i] - m2);
        sum1 += e1[i];
        sum2 += e2[i];
    }
#pragma unroll
    for (int o = 16; o; o >>= 1) {
        sum1 += __shfl_xor_sync(0xffffffffu, sum1, o);
        sum2 += __shfl_xor_sync(0xffffffffu, sum2, o);
    }
    __syncthreads();
    if (lane == 0) { s1[warp] = sum1; s2[warp] = sum2; }
    __syncthreads();
    sum1 = 0.f; sum2 = 0.f;
#pragma unroll
    for (int w = 0; w < 8; w++) { sum1 += s1[w]; sum2 += s2[w]; }

    const float inv1 = 1.f / sum1;
    const float inv2 = g_lambda / sum2;
    uint4 hv;
    hv.x = pack_h(e1[0] * inv1 - e2[0] * inv2, e1[1] * inv1 - e2[1] * inv2);
    hv.y = pack_h(e1[2] * inv1 - e2[2] * inv2, e1[3] * inv1 - e2[3] * inv2);
    hv.z = pack_h(e1[4] * inv1 - e2[4] * inv2, e1[5] * inv1 - e2[5] * inv2);
    hv.w = pack_h(e1[6] * inv1 - e2[6] * inv2, e1[7] * inv1 - e2[7] * inv2);
    *(uint4*)&dh[row * 2048 + t * 8] = hv;
}

// ---------------------------------------------------------------------------
extern "C" void kernel_launch(void* const* d_in, const int* in_sizes, int n_in,
                              void* d_out, int out_size)
{
    const float* x    = (const float*)d_in[0];
    const float* Wqkv = (const float*)d_in[1];
    const float* bqkv = (const float*)d_in[2];
    const float* Wv   = (const float*)d_in[3];
    const float* bv   = (const float*)d_in[4];
    const float* Wo   = (const float*)d_in[5];
    const float* bo   = (const float*)d_in[6];
    const float* lq1  = (const float*)d_in[7];
    const float* lk1  = (const float*)d_in[8];
    const float* lq2  = (const float*)d_in[9];
    const float* lk2  = (const float*)d_in[10];
    float* out = (float*)d_out;

    cudaFuncSetAttribute(bf_gemm<false, 3>, cudaFuncAttributeMaxDynamicSharedMemorySize, DSMEM_BYTES);
    cudaFuncSetAttribute(bf_gemm<true, 3>,  cudaFuncAttributeMaxDynamicSharedMemorySize, DSMEM_BYTES);
    cudaFuncSetAttribute(bf_gemm<false, 1>, cudaFuncAttributeMaxDynamicSharedMemorySize, DSMEM_BYTES);

    float *Mm, *l1, *l2, *cvec;
    fp16 *xh, *xl, *wqh, *wql, *wvh, *wvl, *woh, *wol;
    fp16 *qh, *ql, *mh, *ml, *vph, *dh;
    cudaGetSymbolAddress((void**)&Mm,  g_M);
    cudaGetSymbolAddress((void**)&l1,  g_l1);
    cudaGetSymbolAddress((void**)&l2,  g_l2);
    cudaGetSymbolAddress((void**)&cvec, g_cvec);
    cudaGetSymbolAddress((void**)&xh,  g_xh);   cudaGetSymbolAddress((void**)&xl,  g_xl);
    cudaGetSymbolAddress((void**)&wqh, g_wqh);  cudaGetSymbolAddress((void**)&wql, g_wql);
    cudaGetSymbolAddress((void**)&wvh, g_wvh);  cudaGetSymbolAddress((void**)&wvl, g_wvl);
    cudaGetSymbolAddress((void**)&woh, g_woh);  cudaGetSymbolAddress((void**)&wol, g_wol);
    cudaGetSymbolAddress((void**)&qh,  g_qh);   cudaGetSymbolAddress((void**)&ql,  g_ql);
    cudaGetSymbolAddress((void**)&mh,  g_mh);   cudaGetSymbolAddress((void**)&ml,  g_ml);
    cudaGetSymbolAddress((void**)&vph, g_vph);
    cudaGetSymbolAddress((void**)&dh,  g_dh);

    const long long SQ  = 2048LL * 1024;
    const long long SL  = 2048LL * 2048;
    const long long SV  = 2048LL * 512;

    // #1, #2: input splits needed for qkv
    split_kernel<<<1024, 256>>>((const float4*)x,    (uint4*)xh,  (uint4*)xl,  4096 * 512 / 8);
    split_kernel<<<256,  256>>>((const float4*)Wqkv, (uint4*)wqh, (uint4*)wql, 512 * 1024 / 8);

    // #3: qkv = x @ Wqkv + bqkv -> planes  [4096,1024]   (3-pass)
    bf_gemm<false, 3><<<dim3(8, 32, 1), NTH, DSMEM_BYTES>>>(
        xh, xl, wqh, wql, nullptr, nullptr, qh, ql,
        512, 512, 1024, 1024, 0, 0, 0, 1.f, bqkv, 1, 0);

    // #4: logits merged (z=0,1 -> l1 via Q1/K1; z=2,3 -> l2 via +256 offset)
    bf_gemm<true, 3><<<dim3(16, 16, 4), NTH, DSMEM_BYTES>>>(
        qh + 0, ql + 0, qh + 512, ql + 512, l1, l2, nullptr, nullptr,
        256, 1024, 1024, 2048, SQ, SQ, SL, 0.125f, nullptr, 1, 256);

    // #5, #6: weight splits for the V'-path
    split_kernel<<<2048, 256>>>((const float4*)Wv, (uint4*)wvh, (uint4*)wvl, 512 * 8192 / 8);
    split_kernel<<<2048, 256>>>((const float4*)Wo, (uint4*)woh, (uint4*)wol, 8192 * 512 / 8);

    // M = Wv @ Wo  (fp32, splitK=16), then split to planes
    cudaMemsetAsync(Mm, 0, 512 * 512 * sizeof(float));
    bf_gemm<false, 3><<<dim3(4, 4, 16), NTH, DSMEM_BYTES>>>(
        wvh, wvl, woh, wol, Mm, nullptr, nullptr, nullptr,
        8192, 8192, 512, 512, 0, 0, 0, 1.f, nullptr, 16, 0);
    split_kernel<<<128, 256>>>((const float4*)Mm, (uint4*)mh, (uint4*)ml, 512 * 512 / 8);

    // V' = x @ M -> single fp16 plane  [4096,512]   (3-pass compute)
    bf_gemm<false, 3><<<dim3(4, 32, 1), NTH, DSMEM_BYTES>>>(
        xh, xl, mh, ml, nullptr, nullptr, vph, nullptr,
        512, 512, 512, 512, 0, 0, 0, 1.f, nullptr, 1, 0);

    // scalars (lambda before cvec & softmax)
    lambda_kernel<<<1, 32>>>(lq1, lk1, lq2, lk2);
    cvec_kernel<<<512, 256>>>(bv, Wo, bo);

    // diff = softmax(l1) - lam*softmax(l2) -> single fp16 plane
    softmax_diff_kernel<<<4096, 256>>>(l1, l2, dh);

    // out = diff @ V' + cvec  (fp32, 1-pass fp16, splitK=2)
    cudaMemsetAsync(out, 0, 2 * 2048 * 512 * sizeof(float));
    bf_gemm<false, 1><<<dim3(4, 16, 4), NTH, DSMEM_BYTES>>>(
        dh, nullptr, vph, nullptr, out, nullptr, nullptr, nullptr,
        2048, 2048, 512, 512, SL, SV, SV, 1.f, cvec, 2, 0);
}

// round 16
// speedup vs baseline: 1.0549x; 1.0385x over previous
#include <cuda_runtime.h>
#include <cuda_fp16.h>
#include <math.h>
#include <stdint.h>

// ---------------------------------------------------------------------------
// DifferentialAttention, folded algebra, fp16 hi/lo plane GEMMs.
// R16: qkv + logits GEMMs use 128x256 CTA tiles (32x64 warp tiles) to cut
// ldmatrix bytes/MMA from 170 to 128 (L1tex was the measured 61% bottleneck).
// Pass order hh->lh->hl lets Bl reuse Bh registers (peak ~120 regs).
//   qkv  = x @ Wqkv + bqkv          -> planes      [4096,1024]   (3-pass, 256)
//   M    = Wv @ Wo                  -> fp32 (splitK=16) -> planes (3-pass, 128)
//   V'   = x @ M                    -> single fp16 plane          (3-pass, 128)
//   l1/l2 = Q@K^T * 0.125           -> fp32 (merged z=4)          (3-pass, 256)
//   diff = softmax(l1)-lam*softmax(l2) -> single fp16 plane
//   out  = diff @ V' + cvec         -> fp32 (splitK=2)            (1-pass, 128)
// ---------------------------------------------------------------------------

#define BM 128
#define BKS 32
#define NTH 512
#define NSTAGE 3

typedef __half fp16;

// fp32 scratch
__device__ float g_M[512 * 512];
__device__ float g_l1[2 * 2048 * 2048];
__device__ float g_l2[2 * 2048 * 2048];
__device__ float g_lambda;
__device__ float g_cvec[512];
// fp16 hi/lo planes
__device__ fp16 g_xh[4096 * 512],  g_xl[4096 * 512];
__device__ fp16 g_wqh[512 * 1024], g_wql[512 * 1024];
__device__ fp16 g_wvh[512 * 8192], g_wvl[512 * 8192];
__device__ fp16 g_woh[8192 * 512], g_wol[8192 * 512];
__device__ fp16 g_qh[4096 * 1024], g_ql[4096 * 1024];
__device__ fp16 g_mh[512 * 512],   g_ml[512 * 512];
__device__ fp16 g_vph[4096 * 512];
__device__ fp16 g_dh[2 * 2048 * 2048];

__device__ __forceinline__ void split2(float x, float y, uint32_t& h, uint32_t& l) {
    __half2 H = __floats2half2_rn(x, y);
    float hx = __half2float(__low2half(H));
    float hy = __half2float(__high2half(H));
    __half2 L = __floats2half2_rn(x - hx, y - hy);
    h = *(uint32_t*)&H;
    l = *(uint32_t*)&L;
}
__device__ __forceinline__ uint32_t pack_h(float x, float y) {
    __half2 H = __floats2half2_rn(x, y);
    return *(uint32_t*)&H;
}

__device__ __forceinline__ void mma_fp16(float c[4],
                                         uint32_t a0, uint32_t a1, uint32_t a2, uint32_t a3,
                                         uint32_t b0, uint32_t b1) {
    asm volatile(
        "mma.sync.aligned.m16n8k16.row.col.f32.f16.f16.f32 "
        "{%0,%1,%2,%3}, {%4,%5,%6,%7}, {%8,%9}, {%0,%1,%2,%3};"
        : "+f"(c[0]), "+f"(c[1]), "+f"(c[2]), "+f"(c[3])
        : "r"(a0), "r"(a1), "r"(a2), "r"(a3), "r"(b0), "r"(b1));
}

__device__ __forceinline__ void ldsm_x4(uint32_t& r0, uint32_t& r1, uint32_t& r2, uint32_t& r3,
                                        uint32_t addr) {
    asm volatile("ldmatrix.sync.aligned.m8n8.x4.shared.b16 {%0,%1,%2,%3}, [%4];"
                 : "=r"(r0), "=r"(r1), "=r"(r2), "=r"(r3) : "r"(addr));
}
__device__ __forceinline__ void ldsm_x4t(uint32_t& r0, uint32_t& r1, uint32_t& r2, uint32_t& r3,
                                         uint32_t addr) {
    asm volatile("ldmatrix.sync.aligned.m8n8.x4.trans.shared.b16 {%0,%1,%2,%3}, [%4];"
                 : "=r"(r0), "=r"(r1), "=r"(r2), "=r"(r3) : "r"(addr));
}

__device__ __forceinline__ void cpa16(uint32_t smem, const void* gmem) {
    asm volatile("cp.async.ca.shared.global [%0], [%1], 16;" :: "r"(smem), "l"(gmem));
}
__device__ __forceinline__ void cpa_commit() { asm volatile("cp.async.commit_group;"); }
template <int N>
__device__ __forceinline__ void cpa_wait() { asm volatile("cp.async.wait_group %0;" :: "n"(N)); }

// ---------------------------------------------------------------------------
// fp16 plane GEMM. 512 threads, 16 warps as 4 x 4 of (32 x WN) warp tiles,
// WN = BNT/4. Sub-tile (16-K): A 8KB at +0; B (BNT*64 bytes) at +8192.
// PASSES=3: hi+lo planes, pass order hh, lh, hl. PASSES=1: hi only.
// ---------------------------------------------------------------------------
template <bool TB, int PASSES, int BNT>
__global__ __launch_bounds__(NTH, 1) void bf_gemm(
    const fp16* __restrict__ Ah, const fp16* __restrict__ Al,
    const fp16* __restrict__ Bh, const fp16* __restrict__ Bl,
    float* __restrict__ C, float* __restrict__ Calt,
    fp16* __restrict__ Ch, fp16* __restrict__ Cl,
    int K, int lda, int ldb, int ldc,
    long long sA, long long sB, long long sC,
    float alpha, const float* __restrict__ bias, int splitk, int selOff)
{
    constexpr int WN     = BNT / 4;        // cols per warp
    constexpr int NT     = WN / 8;         // nt count (4 or 8)
    constexpr int NPAIR  = WN / 16;        // 16-col ldsm pairs (2 or 4)
    constexpr int BPLANE = BNT * 32;       // B plane bytes per sub-tile
    constexpr int SUB    = 8192 + 2 * BPLANE;
    constexpr int STAGE  = 2 * SUB;
    constexpr int BROWB  = BNT * 2;        // NN B row bytes
    constexpr int BCH    = BNT * 4;        // B cp.async chunks per sub (2 planes)

    int zb = blockIdx.z / splitk;
    const int kchunk = blockIdx.z % splitk;
    if (Calt) {
        int sel = zb >> 1;
        zb &= 1;
        if (sel) { Ah += selOff; Al += selOff; Bh += selOff; Bl += selOff; C = Calt; }
    }
    const int kc = K / splitk;
    const int kbeg = kchunk * kc;

    Ah += (long long)zb * sA; if (PASSES == 3) Al += (long long)zb * sA;
    Bh += (long long)zb * sB; if (PASSES == 3) Bl += (long long)zb * sB;
    if (C) C += (long long)zb * sC;
    if (Ch) { Ch += (long long)zb * sC; if (Cl) Cl += (long long)zb * sC; }

    const int brow = blockIdx.y * BM;
    const int bcol = blockIdx.x * BNT;
    const int t = threadIdx.x;
    const int lane = t & 31;
    const int wid = t >> 5;
    const int wm = (wid >> 2) * 32;
    const int wn = (wid & 3) * WN;
    const int q = lane & 3;
    const int r = lane >> 2;
    const int lg = lane >> 3;
    const int lr = lane & 7;

    extern __shared__ __align__(128) char sm[];
    const uint32_t sm0 = (uint32_t)__cvta_generic_to_shared(sm);

    float acc[2][8][4];
#pragma unroll
    for (int i = 0; i < 2; i++)
#pragma unroll
        for (int j = 0; j < NT; j++)
#pragma unroll
            for (int c = 0; c < 4; c++) acc[i][j][c] = 0.f;

    auto load_stage = [&](int st, int k0) {
        uint32_t sbase = sm0 + (uint32_t)(st * STAGE);
#pragma unroll
        for (int sub = 0; sub < 2; sub++) {
            uint32_t base = sbase + (uint32_t)(sub * SUB);
            int ks = k0 + sub * 16;
            // A: 512 chunks, 1/thread
            {
                int pl = t >> 8, rem = t & 255;
                if (PASSES == 3 || pl == 0) {
                    int m = rem >> 1, half = rem & 1;
                    const fp16* src = (pl ? Al : Ah) + (long long)(brow + m) * lda + ks + half * 8;
                    cpa16(base + (uint32_t)(pl * 4096 + m * 32 + ((half ^ ((m >> 2) & 1)) * 16)), src);
                }
            }
            // B: BCH chunks, BCH/512 per thread
#pragma unroll
            for (int c = 0; c < BCH / 512; c++) {
                int idx = t + c * 512;
                int pl = idx / (BNT * 2), rem = idx % (BNT * 2);
                if (PASSES == 3 || pl == 0) {
                    if (TB) {
                        int n = rem >> 1, half = rem & 1;
                        const fp16* src = (pl ? Bl : Bh) + (long long)(bcol + n) * ldb + ks + half * 8;
                        cpa16(base + (uint32_t)(8192 + pl * BPLANE + n * 32 +
                                                ((half ^ ((n >> 2) & 1)) * 16)), src);
                    } else {
                        int kk = rem / (BNT / 8), j = rem % (BNT / 8);
                        const fp16* src = (pl ? Bl : Bh) + (long long)(ks + kk) * ldb + bcol + j * 8;
                        cpa16(base + (uint32_t)(8192 + pl * BPLANE + kk * BROWB +
                                                ((j ^ (kk & 7)) * 16)), src);
                    }
                }
            }
        }
        cpa_commit();
    };

    auto ldB = [&](uint32_t base, int pl, uint32_t Bf[8][2]) {
#pragma unroll
        for (int pair = 0; pair < NPAIR; pair++) {
            int nl = pair * 2, nh = pair * 2 + 1;
            if (TB) {
                int row = wn + pair * 16 + lr + (lg & 1) * 8;
                int half = lg >> 1;
                uint32_t a = base + (uint32_t)(8192 + pl * BPLANE + row * 32 +
                                               ((half ^ ((row >> 2) & 1)) * 16));
                ldsm_x4(Bf[nl][0], Bf[nh][0], Bf[nl][1], Bf[nh][1], a);
            } else {
                int krow = lr + (lg & 1) * 8;
                int j = (wn >> 3) + pair * 2 + (lg >> 1);
                uint32_t a = base + (uint32_t)(8192 + pl * BPLANE + krow * BROWB +
                                               ((j ^ (krow & 7)) * 16));
                ldsm_x4t(Bf[nl][0], Bf[nl][1], Bf[nh][0], Bf[nh][1], a);
            }
        }
    };

    auto compute_sub = [&](uint32_t base) {
        uint32_t Ahi[2][4], Alo[2][4];
#pragma unroll
        for (int mt = 0; mt < 2; mt++) {
            int row = wm + mt * 16 + lr + (lg & 1) * 8;
            int half = lg >> 1;
            uint32_t swz = (uint32_t)((half ^ ((row >> 2) & 1)) * 16);
            ldsm_x4(Ahi[mt][0], Ahi[mt][1], Ahi[mt][2], Ahi[mt][3],
                    base + (uint32_t)(row * 32) + swz);
            if (PASSES == 3)
                ldsm_x4(Alo[mt][0], Alo[mt][1], Alo[mt][2], Alo[mt][3],
                        base + (uint32_t)(4096 + row * 32) + swz);
        }
        {
            uint32_t Bhf[8][2];
            ldB(base, 0, Bhf);
            // pass hh
#pragma unroll
            for (int mt = 0; mt < 2; mt++)
#pragma unroll
                for (int nt = 0; nt < NT; nt++)
                    mma_fp16(acc[mt][nt], Ahi[mt][0], Ahi[mt][1], Ahi[mt][2], Ahi[mt][3],
                             Bhf[nt][0], Bhf[nt][1]);
            if (PASSES == 3) {
                // pass lh (Alo x Bh) — Bh dead after this
#pragma unroll
                for (int mt = 0; mt < 2; mt++)
#pragma unroll
                    for (int nt = 0; nt < NT; nt++)
                        mma_fp16(acc[mt][nt], Alo[mt][0], Alo[mt][1], Alo[mt][2], Alo[mt][3],
                                 Bhf[nt][0], Bhf[nt][1]);
            }
        }
        if (PASSES == 3) {
            uint32_t Blf[8][2];
            ldB(base, 1, Blf);
            // pass hl
#pragma unroll
            for (int mt = 0; mt < 2; mt++)
#pragma unroll
                for (int nt = 0; nt < NT; nt++)
                    mma_fp16(acc[mt][nt], Ahi[mt][0], Ahi[mt][1], Ahi[mt][2], Ahi[mt][3],
                             Blf[nt][0], Blf[nt][1]);
        }
    };

    const int nIter = kc / BKS;
    load_stage(0, kbeg);
    if (nIter > 1) load_stage(1, kbeg + BKS);

    for (int it = 0; it < nIter; it++) {
        if (it + 1 < nIter) cpa_wait<1>(); else cpa_wait<0>();
        __syncthreads();
        if (it + 2 < nIter) load_stage((it + 2) % NSTAGE, kbeg + (it + 2) * BKS);

        uint32_t sbase = sm0 + (uint32_t)((it % NSTAGE) * STAGE);
        compute_sub(sbase);
        compute_sub(sbase + SUB);
        __syncthreads();
    }

    // ---- epilogue ----
#pragma unroll
    for (int mt = 0; mt < 2; mt++) {
#pragma unroll
        for (int nt = 0; nt < NT; nt++) {
            int row = brow + wm + mt * 16 + r;
            int col = bcol + wn + nt * 8 + 2 * q;
            float b0 = 0.f, b1 = 0.f;
            if (bias && kchunk == 0) { b0 = bias[col]; b1 = bias[col + 1]; }
            float v0 = alpha * acc[mt][nt][0] + b0;
            float v1 = alpha * acc[mt][nt][1] + b1;
            float v2 = alpha * acc[mt][nt][2] + b0;
            float v3 = alpha * acc[mt][nt][3] + b1;
            if (Ch) {
                if (Cl) {
                    uint32_t h, l;
                    split2(v0, v1, h, l);
                    *(uint32_t*)&Ch[(long long)row * ldc + col] = h;
                    *(uint32_t*)&Cl[(long long)row * ldc + col] = l;
                    split2(v2, v3, h, l);
                    *(uint32_t*)&Ch[(long long)(row + 8) * ldc + col] = h;
                    *(uint32_t*)&Cl[(long long)(row + 8) * ldc + col] = l;
                } else {
                    *(uint32_t*)&Ch[(long long)row * ldc + col] = pack_h(v0, v1);
                    *(uint32_t*)&Ch[(long long)(row + 8) * ldc + col] = pack_h(v2, v3);
                }
            } else if (splitk > 1) {
                atomicAdd(&C[(long long)row * ldc + col], v0);
                atomicAdd(&C[(long long)row * ldc + col + 1], v1);
                atomicAdd(&C[(long long)(row + 8) * ldc + col], v2);
                atomicAdd(&C[(long long)(row + 8) * ldc + col + 1], v3);
            } else {
                *(float2*)&C[(long long)row * ldc + col] = make_float2(v0, v1);
                *(float2*)&C[(long long)(row + 8) * ldc + col] = make_float2(v2, v3);
            }
        }
    }
}

// ---------------------------------------------------------------------------
__global__ void split_kernel(const float4* __restrict__ src,
                             uint4* __restrict__ h, uint4* __restrict__ l, int n8)
{
    int i = blockIdx.x * blockDim.x + threadIdx.x;
    if (i < n8) {
        float4 v0 = src[2 * i];
        float4 v1 = src[2 * i + 1];
        uint4 hv, lv;
        split2(v0.x, v0.y, hv.x, lv.x);
        split2(v0.z, v0.w, hv.y, lv.y);
        split2(v1.x, v1.y, hv.z, lv.z);
        split2(v1.z, v1.w, hv.w, lv.w);
        h[i] = hv;
        l[i] = lv;
    }
}

__global__ void lambda_kernel(const float* __restrict__ lq1, const float* __restrict__ lk1,
                              const float* __restrict__ lq2, const float* __restrict__ lk2)
{
    if (threadIdx.x == 0) {
        float d1 = 0.f, d2 = 0.f;
        for (int i = 0; i < 64; i++) {
            d1 += lq1[i] * lk1[i];
            d2 += lq2[i] * lk2[i];
        }
        g_lambda = expf(d1) - expf(d2) + (0.8f - 0.6f * expf(-0.3f * 0.0f));
    }
}

__global__ __launch_bounds__(256) void cvec_kernel(
    const float* __restrict__ bv, const float* __restrict__ Wo,
    const float* __restrict__ bo)
{
    const int n = blockIdx.x;
    const int t = threadIdx.x;
    float s = 0.f;
    for (int k = t; k < 8192; k += 256)
        s += bv[k] * Wo[(long long)k * 512 + n];
    __shared__ float red[256];
    red[t] = s;
    __syncthreads();
    for (int o = 128; o; o >>= 1) {
        if (t < o) red[t] += red[t + o];
        __syncthreads();
    }
    if (t == 0) g_cvec[n] = bo[n] + (1.f - g_lambda) * red[0];
}

// ---------------------------------------------------------------------------
__global__ __launch_bounds__(256) void softmax_diff_kernel(
    const float* __restrict__ l1, const float* __restrict__ l2,
    fp16* __restrict__ dh)
{
    long long row = blockIdx.x;
    const float* r1 = l1 + row * 2048;
    const float* r2 = l2 + row * 2048;
    const int t = threadIdx.x;
    const int lane = t & 31, warp = t >> 5;

    float v1[8], v2[8];
    *(float4*)&v1[0] = *(const float4*)&r1[t * 8];
    *(float4*)&v1[4] = *(const float4*)&r1[t * 8 + 4];
    *(float4*)&v2[0] = *(const float4*)&r2[t * 8];
    *(float4*)&v2[4] = *(const float4*)&r2[t * 8 + 4];

    float m1 = -1e30f, m2 = -1e30f;
#pragma unroll
    for (int i = 0; i < 8; i++) {
        m1 = fmaxf(m1, v1[i]);
        m2 = fmaxf(m2, v2[i]);
    }
#pragma unroll
    for (int o = 16; o; o >>= 1) {
        m1 = fmaxf(m1, __shfl_xor_sync(0xffffffffu, m1, o));
        m2 = fmaxf(m2, __shfl_xor_sync(0xffffffffu, m2, o));
    }
    __shared__ float s1[8], s2[8];
    if (lane == 0) { s1[warp] = m1; s2[warp] = m2; }
    __syncthreads();
    m1 = s1[0]; m2 = s2[0];
#pragma unroll
    for (int w = 1; w < 8; w++) {
        m1 = fmaxf(m1, s1[w]);
        m2 = fmaxf(m2, s2[w]);
    }

    float e1[8], e2[8];
    float sum1 = 0.f, sum2 = 0.f;
#pragma unroll
    for (int i = 0; i < 8; i++) {
        e1[i] = __expf(v1[i] - m1);
        e2[i] = __expf(v2[i] - m2);
        sum1 += e1[i];
        sum2 += e2[i];
    }
#pragma unroll
    for (int o = 16; o; o >>= 1) {
        sum1 += __shfl_xor_sync(0xffffffffu, sum1, o);
        sum2 += __shfl_xor_sync(0xffffffffu, sum2, o);
    }
    __syncthreads();
    if (lane == 0) { s1[warp] = sum1; s2[warp] = sum2; }
    __syncthreads();
    sum1 = 0.f; sum2 = 0.f;
#pragma unroll
    for (int w = 0; w < 8; w++) { sum1 += s1[w]; sum2 += s2[w]; }

    const float inv1 = 1.f / sum1;
    const float inv2 = g_lambda / sum2;
    uint4 hv;
    hv.x = pack_h(e1[0] * inv1 - e2[0] * inv2, e1[1] * inv1 - e2[1] * inv2);
    hv.y = pack_h(e1[2] * inv1 - e2[2] * inv2, e1[3] * inv1 - e2[3] * inv2);
    hv.z = pack_h(e1[4] * inv1 - e2[4] * inv2, e1[5] * inv1 - e2[5] * inv2);
    hv.w = pack_h(e1[6] * inv1 - e2[6] * inv2, e1[7] * inv1 - e2[7] * inv2);
    *(uint4*)&dh[row * 2048 + t * 8] = hv;
}

// ---------------------------------------------------------------------------
extern "C" void kernel_launch(void* const* d_in, const int* in_sizes, int n_in,
                              void* d_out, int out_size)
{
    const float* x    = (const float*)d_in[0];
    const float* Wqkv = (const float*)d_in[1];
    const float* bqkv = (const float*)d_in[2];
    const float* Wv   = (const float*)d_in[3];
    const float* bv   = (const float*)d_in[4];
    const float* Wo   = (const float*)d_in[5];
    const float* bo   = (const float*)d_in[6];
    const float* lq1  = (const float*)d_in[7];
    const float* lk1  = (const float*)d_in[8];
    const float* lq2  = (const float*)d_in[9];
    const float* lk2  = (const float*)d_in[10];
    float* out = (float*)d_out;

    const int DS128 = NSTAGE * 2 * (8192 + 2 * 128 * 32);   // 98304
    const int DS256 = NSTAGE * 2 * (8192 + 2 * 256 * 32);   // 147456

    cudaFuncSetAttribute(bf_gemm<false, 3, 128>, cudaFuncAttributeMaxDynamicSharedMemorySize, DS128);
    cudaFuncSetAttribute(bf_gemm<false, 1, 128>, cudaFuncAttributeMaxDynamicSharedMemorySize, DS128);
    cudaFuncSetAttribute(bf_gemm<false, 3, 256>, cudaFuncAttributeMaxDynamicSharedMemorySize, DS256);
    cudaFuncSetAttribute(bf_gemm<true, 3, 256>,  cudaFuncAttributeMaxDynamicSharedMemorySize, DS256);

    float *Mm, *l1, *l2, *cvec;
    fp16 *xh, *xl, *wqh, *wql, *wvh, *wvl, *woh, *wol;
    fp16 *qh, *ql, *mh, *ml, *vph, *dh;
    cudaGetSymbolAddress((void**)&Mm,  g_M);
    cudaGetSymbolAddress((void**)&l1,  g_l1);
    cudaGetSymbolAddress((void**)&l2,  g_l2);
    cudaGetSymbolAddress((void**)&cvec, g_cvec);
    cudaGetSymbolAddress((void**)&xh,  g_xh);   cudaGetSymbolAddress((void**)&xl,  g_xl);
    cudaGetSymbolAddress((void**)&wqh, g_wqh);  cudaGetSymbolAddress((void**)&wql, g_wql);
    cudaGetSymbolAddress((void**)&wvh, g_wvh);  cudaGetSymbolAddress((void**)&wvl, g_wvl);
    cudaGetSymbolAddress((void**)&woh, g_woh);  cudaGetSymbolAddress((void**)&wol, g_wol);
    cudaGetSymbolAddress((void**)&qh,  g_qh);   cudaGetSymbolAddress((void**)&ql,  g_ql);
    cudaGetSymbolAddress((void**)&mh,  g_mh);   cudaGetSymbolAddress((void**)&ml,  g_ml);
    cudaGetSymbolAddress((void**)&vph, g_vph);
    cudaGetSymbolAddress((void**)&dh,  g_dh);

    const long long SQ  = 2048LL * 1024;
    const long long SL  = 2048LL * 2048;
    const long long SV  = 2048LL * 512;

    // input splits needed for qkv
    split_kernel<<<1024, 256>>>((const float4*)x,    (uint4*)xh,  (uint4*)xl,  4096 * 512 / 8);
    split_kernel<<<256,  256>>>((const float4*)Wqkv, (uint4*)wqh, (uint4*)wql, 512 * 1024 / 8);

    // qkv = x @ Wqkv + bqkv -> planes  [4096,1024]  (3-pass, 256-wide)
    bf_gemm<false, 3, 256><<<dim3(4, 32, 1), NTH, DS256>>>(
        xh, xl, wqh, wql, nullptr, nullptr, qh, ql,
        512, 512, 1024, 1024, 0, 0, 0, 1.f, bqkv, 1, 0);

    // logits merged (z=0,1 -> l1 via Q1/K1; z=2,3 -> l2 via +256 offset)
    bf_gemm<true, 3, 256><<<dim3(8, 16, 4), NTH, DS256>>>(
        qh + 0, ql + 0, qh + 512, ql + 512, l1, l2, nullptr, nullptr,
        256, 1024, 1024, 2048, SQ, SQ, SL, 0.125f, nullptr, 1, 256);

    // weight splits for the V'-path
    split_kernel<<<2048, 256>>>((const float4*)Wv, (uint4*)wvh, (uint4*)wvl, 512 * 8192 / 8);
    split_kernel<<<2048, 256>>>((const float4*)Wo, (uint4*)woh, (uint4*)wol, 8192 * 512 / 8);

    // M = Wv @ Wo  (fp32, splitK=16), then split to planes
    cudaMemsetAsync(Mm, 0, 512 * 512 * sizeof(float));
    bf_gemm<false, 3, 128><<<dim3(4, 4, 16), NTH, DS128>>>(
        wvh, wvl, woh, wol, Mm, nullptr, nullptr, nullptr,
        8192, 8192, 512, 512, 0, 0, 0, 1.f, nullptr, 16, 0);
    split_kernel<<<128, 256>>>((const float4*)Mm, (uint4*)mh, (uint4*)ml, 512 * 512 / 8);

    // V' = x @ M -> single fp16 plane  [4096,512]
    bf_gemm<false, 3, 128><<<dim3(4, 32, 1), NTH, DS128>>>(
        xh, xl, mh, ml, nullptr, nullptr, vph, nullptr,
        512, 512, 512, 512, 0, 0, 0, 1.f, nullptr, 1, 0);

    // scalars
    lambda_kernel<<<1, 32>>>(lq1, lk1, lq2, lk2);
    cvec_kernel<<<512, 256>>>(bv, Wo, bo);

    // diff = softmax(l1) - lam*softmax(l2) -> single fp16 plane
    softmax_diff_kernel<<<4096, 256>>>(l1, l2, dh);

    // out = diff @ V' + cvec  (fp32, 1-pass fp16, splitK=2)
    cudaMemsetAsync(out, 0, 2 * 2048 * 512 * sizeof(float));
    bf_gemm<false, 1, 128><<<dim3(4, 16, 4), NTH, DS128>>>(
        dh, nullptr, vph, nullptr, out, nullptr, nullptr, nullptr,
        2048, 2048, 512, 512, SL, SV, SV, 1.f, cvec, 2, 0);
}